// round 1
// baseline (speedup 1.0000x reference)
#include <cuda_runtime.h>
#include <math.h>

// ZINBDecoder: per-edge h = ufeats[src] * ifeats[dst]  (d=128)
//   mu_  = sigmoid(h . W_mean + b_mean)
//   d_   = h . W_disp + b_disp
//   pi   = sigmoid(h . W_pi + b_pi)
//   disp = clip(softplus(gef * d_), 1e-4, 1e4)
//   mu   = szf * clip(exp(gef * mu_) - 1, 1e-5, 1e6)
// Output layout: [mu(0..E), disp(E..2E), pi(2E..3E)], float32.

#define D 128
#define D4 (D / 4)   // 32 float4 per row -> one lane each

__device__ __forceinline__ float warp_sum(float v) {
#pragma unroll
    for (int off = 16; off > 0; off >>= 1)
        v += __shfl_xor_sync(0xFFFFFFFFu, v, off);
    return v;
}

__device__ __forceinline__ float sigmoidf_(float x) {
    return 1.0f / (1.0f + expf(-x));
}

__device__ __forceinline__ float softplusf_(float x) {
    // stable: max(x,0) + log1p(exp(-|x|))
    return fmaxf(x, 0.0f) + log1pf(expf(-fabsf(x)));
}

__global__ void __launch_bounds__(256, 8)
zinb_decoder_kernel(const float* __restrict__ ufeats,
                    const float* __restrict__ ifeats,
                    const float* __restrict__ ge_factor,
                    const float* __restrict__ sz_factor,
                    const float* __restrict__ W_mean,
                    const float* __restrict__ b_mean,
                    const float* __restrict__ W_disp,
                    const float* __restrict__ b_disp,
                    const float* __restrict__ W_pi,
                    const float* __restrict__ b_pi,
                    const int*   __restrict__ src_idx,
                    const int*   __restrict__ dst_idx,
                    float* __restrict__ out,
                    int E)
{
    const int lane   = threadIdx.x & 31;
    const int gwarp  = (blockIdx.x * blockDim.x + threadIdx.x) >> 5;
    const int nwarps = (gridDim.x * blockDim.x) >> 5;

    // Per-lane weight slices live in registers for the whole kernel.
    const float4 wm = reinterpret_cast<const float4*>(W_mean)[lane];
    const float4 wd = reinterpret_cast<const float4*>(W_disp)[lane];
    const float4 wp = reinterpret_cast<const float4*>(W_pi)[lane];
    const float  bm = b_mean[0];
    const float  bd = b_disp[0];
    const float  bp = b_pi[0];

    const float4* __restrict__ u4 = reinterpret_cast<const float4*>(ufeats);
    const float4* __restrict__ v4 = reinterpret_cast<const float4*>(ifeats);

    for (int e = gwarp; e < E; e += nwarps) {
        const int s = src_idx[e];   // broadcast load (all lanes same addr)
        const int g = dst_idx[e];

        const float4 u = u4[s * D4 + lane];
        const float4 v = v4[g * D4 + lane];

        const float hx = u.x * v.x;
        const float hy = u.y * v.y;
        const float hz = u.z * v.z;
        const float hw = u.w * v.w;

        float sm = fmaf(hx, wm.x, fmaf(hy, wm.y, fmaf(hz, wm.z, hw * wm.w)));
        float sd = fmaf(hx, wd.x, fmaf(hy, wd.y, fmaf(hz, wd.z, hw * wd.w)));
        float sp = fmaf(hx, wp.x, fmaf(hy, wp.y, fmaf(hz, wp.z, hw * wp.w)));

        sm = warp_sum(sm);
        sd = warp_sum(sd);
        sp = warp_sum(sp);

        if (lane == 0) {
            const float gef = ge_factor[g];
            const float szf = sz_factor[s];

            const float mu_sig = sigmoidf_(sm + bm);
            const float pi_v   = sigmoidf_(sp + bp);
            const float d_lin  = sd + bd;

            float disp = softplusf_(gef * d_lin);
            disp = fminf(fmaxf(disp, 1e-4f), 1e4f);

            float mu = expf(gef * mu_sig) - 1.0f;
            mu = fminf(fmaxf(mu, 1e-5f), 1e6f);
            mu *= szf;

            out[e]         = mu;
            out[E + e]     = disp;
            out[2 * E + e] = pi_v;
        }
    }
}

extern "C" void kernel_launch(void* const* d_in, const int* in_sizes, int n_in,
                              void* d_out, int out_size)
{
    const float* ufeats    = (const float*)d_in[0];
    const float* ifeats    = (const float*)d_in[1];
    const float* ge_factor = (const float*)d_in[2];
    const float* sz_factor = (const float*)d_in[3];
    const float* W_mean    = (const float*)d_in[4];
    const float* b_mean    = (const float*)d_in[5];
    const float* W_disp    = (const float*)d_in[6];
    const float* b_disp    = (const float*)d_in[7];
    const float* W_pi      = (const float*)d_in[8];
    const float* b_pi      = (const float*)d_in[9];
    const int*   src_idx   = (const int*)d_in[10];
    const int*   dst_idx   = (const int*)d_in[11];
    float* out = (float*)d_out;

    const int E = in_sizes[10];

    // Persistent-ish grid: 3552 blocks x 8 warps = 28416 warps, grid-stride.
    const int threads = 256;
    int blocks = 148 * 24;
    const int warps_needed = (E + 0) ;
    (void)warps_needed; (void)out_size; (void)n_in;
    // Don't launch more warps than edges.
    long long total_warps = (long long)blocks * (threads / 32);
    if (total_warps > E) blocks = (int)((E + (threads / 32) - 1) / (threads / 32));

    zinb_decoder_kernel<<<blocks, threads>>>(
        ufeats, ifeats, ge_factor, sz_factor,
        W_mean, b_mean, W_disp, b_disp, W_pi, b_pi,
        src_idx, dst_idx, out, E);
}

// round 2
// speedup vs baseline: 1.9168x; 1.9168x over previous
#include <cuda_runtime.h>
#include <math.h>

// ZINBDecoder, 4 lanes per edge, 8 edges per warp.
//   h = ufeats[src] * ifeats[dst]  (d=128)
//   mu_  = sigmoid(h.Wm + bm); d_ = h.Wd + bd; pi = sigmoid(h.Wp + bp)
//   disp = clip(softplus(gef*d_), 1e-4, 1e4)
//   mu   = szf * clip(exp(gef*mu_) - 1, 1e-5, 1e6)
// out = [mu | disp | pi], fp32.

#define D4 32   // float4 chunks per 128-float row

__device__ __forceinline__ float fast_sigmoid(float x) {
    // 1 / (1 + e^-x); __expf(inf)->inf, 1/inf->0: correct saturation.
    return __fdividef(1.0f, 1.0f + __expf(-x));
}

__global__ void __launch_bounds__(256)
zinb_kernel(const float* __restrict__ ufeats,
            const float* __restrict__ ifeats,
            const float* __restrict__ ge_factor,
            const float* __restrict__ sz_factor,
            const float* __restrict__ W_mean,
            const float* __restrict__ b_mean,
            const float* __restrict__ W_disp,
            const float* __restrict__ b_disp,
            const float* __restrict__ W_pi,
            const float* __restrict__ b_pi,
            const int*   __restrict__ src_idx,
            const int*   __restrict__ dst_idx,
            float* __restrict__ out,
            int E)
{
    __shared__ float4 sWm[D4], sWd[D4], sWp[D4];

    const int tid = threadIdx.x;
    if (tid < 32)       sWm[tid]      = reinterpret_cast<const float4*>(W_mean)[tid];
    else if (tid < 64)  sWd[tid - 32] = reinterpret_cast<const float4*>(W_disp)[tid - 32];
    else if (tid < 96)  sWp[tid - 64] = reinterpret_cast<const float4*>(W_pi)[tid - 64];
    __syncthreads();

    const int lane = tid & 31;
    const int sub  = lane & 3;        // position within 4-lane group
    const int grp  = lane >> 2;       // edge slot within warp (0..7)

    const long long gwarp = (long long)((blockIdx.x * blockDim.x + tid) >> 5);
    const long long e_ll  = gwarp * 8 + grp;
    const bool      valid = (e_ll < (long long)E);
    const int       e     = valid ? (int)e_ll : (E - 1);   // clamp for safe loads

    const int s = src_idx[e];
    const int g = dst_idx[e];

    const float4* __restrict__ u4 =
        reinterpret_cast<const float4*>(ufeats) + (size_t)s * D4 + sub;
    const float4* __restrict__ v4 =
        reinterpret_cast<const float4*>(ifeats) + (size_t)g * D4 + sub;

    float sm = 0.0f, sd = 0.0f, sp = 0.0f;

#pragma unroll
    for (int k = 0; k < 8; ++k) {
        const float4 u  = u4[k * 4];
        const float4 v  = v4[k * 4];
        const float4 wm = sWm[k * 4 + sub];
        const float4 wd = sWd[k * 4 + sub];
        const float4 wp = sWp[k * 4 + sub];

        const float hx = u.x * v.x;
        const float hy = u.y * v.y;
        const float hz = u.z * v.z;
        const float hw = u.w * v.w;

        sm = fmaf(hx, wm.x, fmaf(hy, wm.y, fmaf(hz, wm.z, fmaf(hw, wm.w, sm))));
        sd = fmaf(hx, wd.x, fmaf(hy, wd.y, fmaf(hz, wd.z, fmaf(hw, wd.w, sd))));
        sp = fmaf(hx, wp.x, fmaf(hy, wp.y, fmaf(hz, wp.z, fmaf(hw, wp.w, sp))));
    }

    // Reduce within each 4-lane group (xor 1, xor 2 stay inside the group).
    sm += __shfl_xor_sync(0xFFFFFFFFu, sm, 1);
    sm += __shfl_xor_sync(0xFFFFFFFFu, sm, 2);
    sd += __shfl_xor_sync(0xFFFFFFFFu, sd, 1);
    sd += __shfl_xor_sync(0xFFFFFFFFu, sd, 2);
    sp += __shfl_xor_sync(0xFFFFFFFFu, sp, 1);
    sp += __shfl_xor_sync(0xFFFFFFFFu, sp, 2);

    // 8 leader lanes (one per edge) apply activations in parallel.
    if (sub == 0 && valid) {
        const float gef = ge_factor[g];
        const float szf = sz_factor[s];
        const float bm  = b_mean[0];
        const float bd  = b_disp[0];
        const float bp  = b_pi[0];

        const float mu_sig = fast_sigmoid(sm + bm);
        const float pi_v   = fast_sigmoid(sp + bp);
        const float d_lin  = sd + bd;

        // stable softplus
        const float x    = gef * d_lin;
        float disp = fmaxf(x, 0.0f) + log1pf(__expf(-fabsf(x)));
        disp = fminf(fmaxf(disp, 1e-4f), 1e4f);

        float mu = __expf(gef * mu_sig) - 1.0f;   // arg in [0,1]
        mu = fminf(fmaxf(mu, 1e-5f), 1e6f);
        mu *= szf;

        out[e]         = mu;
        out[E + e]     = disp;
        out[2 * E + e] = pi_v;
    }
}

extern "C" void kernel_launch(void* const* d_in, const int* in_sizes, int n_in,
                              void* d_out, int out_size)
{
    const float* ufeats    = (const float*)d_in[0];
    const float* ifeats    = (const float*)d_in[1];
    const float* ge_factor = (const float*)d_in[2];
    const float* sz_factor = (const float*)d_in[3];
    const float* W_mean    = (const float*)d_in[4];
    const float* b_mean    = (const float*)d_in[5];
    const float* W_disp    = (const float*)d_in[6];
    const float* b_disp    = (const float*)d_in[7];
    const float* W_pi      = (const float*)d_in[8];
    const float* b_pi      = (const float*)d_in[9];
    const int*   src_idx   = (const int*)d_in[10];
    const int*   dst_idx   = (const int*)d_in[11];
    float* out = (float*)d_out;
    (void)n_in; (void)out_size;

    const int E = in_sizes[10];

    // 256 threads = 8 warps = 64 edges per block, single pass.
    const int threads = 256;
    const int edges_per_block = 64;
    const int blocks = (E + edges_per_block - 1) / edges_per_block;

    zinb_kernel<<<blocks, threads>>>(
        ufeats, ifeats, ge_factor, sz_factor,
        W_mean, b_mean, W_disp, b_disp, W_pi, b_pi,
        src_idx, dst_idx, out, E);
}

// round 3
// speedup vs baseline: 2.0846x; 1.0875x over previous
#include <cuda_runtime.h>
#include <math.h>

// ZINBDecoder, 8 lanes per edge, 4 edges per warp, packed f32x2 math.
//   h = ufeats[src] * ifeats[dst]  (d=128)
//   mu_  = sigmoid(h.Wm + bm); d_ = h.Wd + bd; pi = sigmoid(h.Wp + bp)
//   disp = clip(softplus(gef*d_), 1e-4, 1e4)
//   mu   = szf * clip(exp(gef*mu_) - 1, 1e-5, 1e6)
// out = [mu | disp | pi], fp32.

#define DV 32   // 16-byte vectors per 128-float row

__device__ __forceinline__ unsigned long long fmul2(unsigned long long a,
                                                    unsigned long long b) {
    unsigned long long d;
    asm("mul.rn.f32x2 %0, %1, %2;" : "=l"(d) : "l"(a), "l"(b));
    return d;
}

__device__ __forceinline__ unsigned long long ffma2(unsigned long long a,
                                                    unsigned long long b,
                                                    unsigned long long c) {
    unsigned long long d;
    asm("fma.rn.f32x2 %0, %1, %2, %3;" : "=l"(d) : "l"(a), "l"(b), "l"(c));
    return d;
}

__device__ __forceinline__ float unpack_sum(unsigned long long p) {
    unsigned int lo, hi;
    asm("mov.b64 {%0, %1}, %2;" : "=r"(lo), "=r"(hi) : "l"(p));
    return __uint_as_float(lo) + __uint_as_float(hi);
}

__device__ __forceinline__ float fast_sigmoid(float x) {
    return __fdividef(1.0f, 1.0f + __expf(-x));
}

__global__ void __launch_bounds__(256)
zinb_kernel(const float* __restrict__ ufeats,
            const float* __restrict__ ifeats,
            const float* __restrict__ ge_factor,
            const float* __restrict__ sz_factor,
            const float* __restrict__ W_mean,
            const float* __restrict__ b_mean,
            const float* __restrict__ W_disp,
            const float* __restrict__ b_disp,
            const float* __restrict__ W_pi,
            const float* __restrict__ b_pi,
            const int*   __restrict__ src_idx,
            const int*   __restrict__ dst_idx,
            float* __restrict__ out,
            int E)
{
    const int tid  = threadIdx.x;
    const int lane = tid & 31;
    const int sub  = lane & 7;        // lane within 8-lane edge group
    const int grp  = lane >> 3;       // edge slot within warp (0..3)

    // Uniform biases, hoisted.
    const float bm = b_mean[0];
    const float bd = b_disp[0];
    const float bp = b_pi[0];

    // Per-thread weight slices in registers: k = 0..3, element (k*8 + sub).
    const ulonglong2* __restrict__ wm2 = reinterpret_cast<const ulonglong2*>(W_mean);
    const ulonglong2* __restrict__ wd2 = reinterpret_cast<const ulonglong2*>(W_disp);
    const ulonglong2* __restrict__ wp2 = reinterpret_cast<const ulonglong2*>(W_pi);
    ulonglong2 wm[4], wd[4], wp[4];
#pragma unroll
    for (int k = 0; k < 4; ++k) {
        wm[k] = wm2[k * 8 + sub];
        wd[k] = wd2[k * 8 + sub];
        wp[k] = wp2[k * 8 + sub];
    }

    const long long gwarp = (long long)((blockIdx.x * blockDim.x + tid) >> 5);
    const long long e_ll  = gwarp * 4 + grp;
    const bool      valid = (e_ll < (long long)E);
    const int       e     = valid ? (int)e_ll : (E - 1);   // clamp for safe loads

    const int s = src_idx[e];
    const int g = dst_idx[e];

    const ulonglong2* __restrict__ u2 =
        reinterpret_cast<const ulonglong2*>(ufeats) + (size_t)s * DV + sub;
    const ulonglong2* __restrict__ v2 =
        reinterpret_cast<const ulonglong2*>(ifeats) + (size_t)g * DV + sub;

    unsigned long long am = 0, ad = 0, ap = 0;   // f32x2 accumulators (0.0f,0.0f)

#pragma unroll
    for (int k = 0; k < 4; ++k) {
        const ulonglong2 u = u2[k * 8];
        const ulonglong2 v = v2[k * 8];

        const unsigned long long h01 = fmul2(u.x, v.x);
        const unsigned long long h23 = fmul2(u.y, v.y);

        am = ffma2(h01, wm[k].x, am);
        am = ffma2(h23, wm[k].y, am);
        ad = ffma2(h01, wd[k].x, ad);
        ad = ffma2(h23, wd[k].y, ad);
        ap = ffma2(h01, wp[k].x, ap);
        ap = ffma2(h23, wp[k].y, ap);
    }

    float sm = unpack_sum(am);
    float sd = unpack_sum(ad);
    float sp = unpack_sum(ap);

    // Reduce within each 8-lane group (xor 1,2,4 stay inside the group).
#pragma unroll
    for (int off = 1; off <= 4; off <<= 1) {
        sm += __shfl_xor_sync(0xFFFFFFFFu, sm, off);
        sd += __shfl_xor_sync(0xFFFFFFFFu, sd, off);
        sp += __shfl_xor_sync(0xFFFFFFFFu, sp, off);
    }

    // 4 leader lanes (one per edge) apply activations in parallel.
    if (sub == 0 && valid) {
        const float gef = ge_factor[g];
        const float szf = sz_factor[s];

        const float mu_sig = fast_sigmoid(sm + bm);
        const float pi_v   = fast_sigmoid(sp + bp);

        // stable softplus: max(x,0) + log(1 + exp(-|x|))
        const float x = gef * (sd + bd);
        float disp = fmaxf(x, 0.0f) + __logf(1.0f + __expf(-fabsf(x)));
        disp = fminf(fmaxf(disp, 1e-4f), 1e4f);

        float mu = __expf(gef * mu_sig) - 1.0f;   // arg in [0,1]
        mu = fminf(fmaxf(mu, 1e-5f), 1e6f);
        mu *= szf;

        out[e]         = mu;
        out[E + e]     = disp;
        out[2 * E + e] = pi_v;
    }
}

extern "C" void kernel_launch(void* const* d_in, const int* in_sizes, int n_in,
                              void* d_out, int out_size)
{
    const float* ufeats    = (const float*)d_in[0];
    const float* ifeats    = (const float*)d_in[1];
    const float* ge_factor = (const float*)d_in[2];
    const float* sz_factor = (const float*)d_in[3];
    const float* W_mean    = (const float*)d_in[4];
    const float* b_mean    = (const float*)d_in[5];
    const float* W_disp    = (const float*)d_in[6];
    const float* b_disp    = (const float*)d_in[7];
    const float* W_pi      = (const float*)d_in[8];
    const float* b_pi      = (const float*)d_in[9];
    const int*   src_idx   = (const int*)d_in[10];
    const int*   dst_idx   = (const int*)d_in[11];
    float* out = (float*)d_out;
    (void)n_in; (void)out_size;

    const int E = in_sizes[10];

    // 256 threads = 8 warps = 32 edges per block, single pass.
    const int threads = 256;
    const int edges_per_block = 32;
    const int blocks = (E + edges_per_block - 1) / edges_per_block;

    zinb_kernel<<<blocks, threads>>>(
        ufeats, ifeats, ge_factor, sz_factor,
        W_mean, b_mean, W_disp, b_disp, W_pi, b_pi,
        src_idx, dst_idx, out, E);
}